// round 8
// baseline (speedup 1.0000x reference)
#include <cuda_runtime.h>
#include <cuda_fp16.h>
#include <cstdint>
#include <cstddef>

#define BROWS 4096
#define DIN   1024
#define DOUT  1024
#define LEAF  32
#define NTOT  (DOUT * LEAF)   // 32768

// ---------------- scratch (device globals: allocation-free) ----------------
__device__ __align__(128) __half d_xb[(size_t)BROWS * DIN];     // 8 MB   x fp16
__device__ __align__(128) __half d_pwb[(size_t)NTOT * DIN];     // 64 MB  pw packed [n=o*32+l][k=i]
__device__ __align__(128) float  d_gate[(size_t)BROWS * LEAF];  // 512 KB gates

// ---------------- helpers ----------------
static __device__ __forceinline__ uint32_t smem_u32(const void* p) {
    uint32_t a;
    asm("{ .reg .u64 t; cvta.to.shared.u64 t, %1; cvt.u32.u64 %0, t; }" : "=r"(a) : "l"(p));
    return a;
}
static __device__ __forceinline__ uint32_t swz(uint32_t o) {     // Swizzle<3,4,3>, 128B rows
    return o ^ ((o >> 3) & 0x70);
}
static __device__ __forceinline__ void cp_async16(uint32_t s, const void* g) {
    asm volatile("cp.async.cg.shared.global [%0], [%1], 16;" :: "r"(s), "l"(g));
}
static __device__ __forceinline__ void ldsm4(uint32_t* r, uint32_t addr) {
    asm volatile("ldmatrix.sync.aligned.m8n8.x4.shared.b16 {%0,%1,%2,%3}, [%4];"
                 : "=r"(r[0]), "=r"(r[1]), "=r"(r[2]), "=r"(r[3]) : "r"(addr));
}
static __device__ __forceinline__ void mma16816(float* d, const uint32_t* a,
                                                uint32_t b0, uint32_t b1) {
    asm volatile("mma.sync.aligned.m16n8k16.row.col.f32.f16.f16.f32 "
                 "{%0,%1,%2,%3}, {%4,%5,%6,%7}, {%8,%9}, {%0,%1,%2,%3};"
                 : "+f"(d[0]), "+f"(d[1]), "+f"(d[2]), "+f"(d[3])
                 : "r"(a[0]), "r"(a[1]), "r"(a[2]), "r"(a[3]), "r"(b0), "r"(b1));
}

// ---------------- kernel 1: gating softmax + x fp32->fp16 (fused) ----------------
__global__ void gating_kernel(const float* __restrict__ x, const float* __restrict__ gw,
                              const float* __restrict__ gb) {
    int row  = (blockIdx.x * blockDim.x + threadIdx.x) >> 5;
    int lane = threadIdx.x & 31;
    if (row >= BROWS) return;
    const float4* xr = reinterpret_cast<const float4*>(x + (size_t)row * DIN);
    float acc = gb[lane];
    #pragma unroll 4
    for (int j = 0; j < DIN / 4; ++j) {
        float4 xv = xr[j];                                 // broadcast load
        int i = j * 4;
        acc = fmaf(xv.x, gw[(i + 0) * LEAF + lane], acc);
        acc = fmaf(xv.y, gw[(i + 1) * LEAF + lane], acc);
        acc = fmaf(xv.z, gw[(i + 2) * LEAF + lane], acc);
        acc = fmaf(xv.w, gw[(i + 3) * LEAF + lane], acc);
    }
    // second pass: lane-owned chunks, L1-hot, coalesced 8B stores
    __half2* hp = reinterpret_cast<__half2*>(d_xb + (size_t)row * DIN);
    #pragma unroll
    for (int jj = 0; jj < 8; ++jj) {
        int j = jj * 32 + lane;
        float4 xv = xr[j];
        hp[j * 2 + 0] = __floats2half2_rn(xv.x, xv.y);
        hp[j * 2 + 1] = __floats2half2_rn(xv.z, xv.w);
    }
    float m = acc;
    #pragma unroll
    for (int o = 16; o; o >>= 1) m = fmaxf(m, __shfl_xor_sync(0xffffffff, m, o));
    float e = expf(acc - m);
    float s = e;
    #pragma unroll
    for (int o = 16; o; o >>= 1) s += __shfl_xor_sync(0xffffffff, s, o);
    d_gate[(size_t)row * LEAF + lane] = e / s;
}

// ---------------- kernel 2: pack pw [O,I,L] fp32 -> pwb [(o*32+l), i] fp16 ----------------
__global__ void pack_pw_kernel(const float* __restrict__ pw) {
    __shared__ float tile[64][33];                        // 64 i  x 32 l  (padded)
    const int o   = blockIdx.x;                           // 0..1023
    const int i0  = blockIdx.y * 64;                      // 0..960
    const int tid = threadIdx.x;                          // 256 threads
    const float* src = pw + ((size_t)o * DIN + i0) * LEAF;
    #pragma unroll
    for (int u = 0; u < 8; ++u) {                         // 2048 coalesced fp32 reads
        int idx = u * 256 + tid;
        tile[idx >> 5][idx & 31] = src[idx];
    }
    __syncthreads();
    __half2* dst2 = reinterpret_cast<__half2*>(d_pwb + ((size_t)o * LEAF) * DIN + i0);
    #pragma unroll
    for (int u = 0; u < 4; ++u) {                         // 1024 coalesced half2 writes
        int idx = u * 256 + tid;
        int l = idx >> 5, p = idx & 31;
        dst2[(size_t)l * (DIN / 2) + p] =
            __floats2half2_rn(tile[2 * p][l], tile[2 * p + 1][l]);
    }
}

// ---------------- kernel 3: mma.sync GEMM, paired k-tiles, fused epilogue ----------------
#define MT  128
#define NT  256
#define KT  64                       // halves per k-tile (128 B rows)
#define KI  (DIN / KT)               // 16 k-tiles -> 8 pairs
#define NPAIR (KI / 2)
#define SA_BYTES    (MT * KT * 2)    // 16384
#define SB_BYTES    (NT * KT * 2)    // 32768
#define STAGE_BYTES (SA_BYTES + SB_BYTES)  // 49152
#define OFF_GS    0                  // gates [128][33] fp32 = 16896
#define OFF_PBS   16896              // pb    [8][33]   fp32 = 1056
#define OFF_TILES 18432              // 1024-aligned
#define SMEM_TOTAL (OFF_TILES + 4 * STAGE_BYTES)  // 215040 B

static __device__ __forceinline__ void load_tile(uint32_t sb, int tid,
                                                 int m_base, int n_base, int ki, int buf) {
    const uint32_t abase = sb + OFF_TILES + buf * STAGE_BYTES;
    const uint32_t bbase = abase + SA_BYTES;
    const __half* ga  = d_xb  + (size_t)m_base * DIN + ki * KT;
    const __half* gbp = d_pwb + (size_t)n_base * DIN + ki * KT;
    #pragma unroll
    for (int u = 0; u < 12; ++u) {                        // 3072 x 16B chunks / 256 thr
        const int idx = u * 256 + tid;
        if (idx < 1024) {                                 // A: 128 rows x 8 chunks
            const int r = idx >> 3, c = idx & 7;
            cp_async16(abase + swz((uint32_t)(r * 128 + c * 16)),
                       ga + (size_t)r * DIN + c * 8);
        } else {                                          // B: 256 rows x 8 chunks
            const int j = idx - 1024;
            const int r = j >> 3, c = j & 7;
            cp_async16(bbase + swz((uint32_t)(r * 128 + c * 16)),
                       gbp + (size_t)r * DIN + c * 8);
        }
    }
}

__global__ void __launch_bounds__(256, 1)
moe_gemm_kernel(float* __restrict__ out, const float* __restrict__ pb) {
    extern __shared__ char smem[];
    const uint32_t sb = smem_u32(smem);
    const int tid    = threadIdx.x;
    const int lane   = tid & 31;
    const int wid    = tid >> 5;                // 8 warps: 2(m) x 4(n)
    const int warp_n = wid & 3;                 // 4 n-warps x 64 cols
    const int warp_m = wid >> 2;                // 2 m-warps x 64 rows
    const int m_tile = blockIdx.x & 31;         // bid = n_tile*32 + m_tile (B panel L2 reuse)
    const int n_tile = blockIdx.x >> 5;
    const int m_base = m_tile * MT;
    const int n_base = n_tile * NT;
    const int o_base = n_tile * 8;              // NT=256 cols = 8 outputs x 32 leaves

    float* gs  = reinterpret_cast<float*>(smem + OFF_GS);    // [128][33]
    float* pbs = reinterpret_cast<float*>(smem + OFF_PBS);   // [8][33]
    #pragma unroll
    for (int i = tid; i < MT * LEAF; i += 256) {
        int r = i >> 5, l = i & 31;
        gs[r * 33 + l] = d_gate[(size_t)(m_base + r) * LEAF + l];
    }
    pbs[(tid >> 5) * 33 + (tid & 31)] = pb[(o_base + (tid >> 5)) * LEAF + (tid & 31)];

    // prologue: pair 0 -> half 0 (bufs 0,1)
    load_tile(sb, tid, m_base, n_base, 0, 0);
    load_tile(sb, tid, m_base, n_base, 1, 1);
    asm volatile("cp.async.commit_group;" ::: "memory");

    float acc[4][8][4];
    #pragma unroll
    for (int a = 0; a < 4; ++a)
        #pragma unroll
        for (int b = 0; b < 8; ++b)
            #pragma unroll
            for (int c = 0; c < 4; ++c) acc[a][b][c] = 0.f;

    const uint32_t arow = (uint32_t)(warp_m * 64 + (lane & 15));
    const uint32_t brow = (uint32_t)(warp_n * 64 + (lane & 7) + ((lane & 16) ? 8 : 0));

    #pragma unroll 1
    for (int p = 0; p < NPAIR; ++p) {
        asm volatile("cp.async.wait_group 0;" ::: "memory");   // pair p resident
        __syncthreads();                                       // + other half free to overwrite
        if (p + 1 < NPAIR) {                                   // prefetch pair p+1 -> other half
            const int nhalf = (p + 1) & 1;
            load_tile(sb, tid, m_base, n_base, 2 * (p + 1),     nhalf * 2);
            load_tile(sb, tid, m_base, n_base, 2 * (p + 1) + 1, nhalf * 2 + 1);
            asm volatile("cp.async.commit_group;" ::: "memory");
        }
        const uint32_t hbase = sb + OFF_TILES + (uint32_t)((p & 1) * 2) * STAGE_BYTES;
        #pragma unroll
        for (int s = 0; s < 2; ++s) {                          // 2 k-tiles in this half
            const uint32_t abase = hbase + (uint32_t)s * STAGE_BYTES;
            const uint32_t bbase = abase + SA_BYTES;
            #pragma unroll
            for (int ks = 0; ks < 4; ++ks) {
                const uint32_t akh = (uint32_t)(ks * 16 + ((lane >> 4) << 3));
                const uint32_t bkh = (uint32_t)(ks * 16 + ((lane >> 3) & 1) * 8);
                uint32_t A[4][4];
                #pragma unroll
                for (int q = 0; q < 4; ++q)
                    ldsm4(A[q], abase + swz((arow + (uint32_t)(q * 16)) * 128 + akh * 2));
                uint32_t Bf[4][4];
                #pragma unroll
                for (int q = 0; q < 4; ++q)
                    ldsm4(Bf[q], bbase + swz((brow + (uint32_t)(q * 16)) * 128 + bkh * 2));
                #pragma unroll
                for (int mf = 0; mf < 4; ++mf)
                    #pragma unroll
                    for (int nf = 0; nf < 8; ++nf)
                        mma16816(acc[mf][nf], A[mf],
                                 Bf[nf >> 1][(nf & 1) * 2], Bf[nf >> 1][(nf & 1) * 2 + 1]);
            }
        }
    }

    // epilogue: out[b,o] = sum_l (D[b,(o,l)] + pb[o,l]) * g[b,l]
    #pragma unroll
    for (int mf = 0; mf < 4; ++mf) {
        #pragma unroll
        for (int rh = 0; rh < 2; ++rh) {
            const int mrow = warp_m * 64 + mf * 16 + (lane >> 2) + rh * 8;
            #pragma unroll
            for (int og = 0; og < 2; ++og) {
                const int o_loc = warp_n * 2 + og;
                float a = 0.f;
                #pragma unroll
                for (int nf4 = 0; nf4 < 4; ++nf4) {
                    const int nf = og * 4 + nf4;
                    const int l  = nf4 * 8 + (lane & 3) * 2;
                    a = fmaf(acc[mf][nf][rh * 2 + 0] + pbs[o_loc * 33 + l],
                             gs[mrow * 33 + l], a);
                    a = fmaf(acc[mf][nf][rh * 2 + 1] + pbs[o_loc * 33 + l + 1],
                             gs[mrow * 33 + l + 1], a);
                }
                a += __shfl_xor_sync(0xffffffff, a, 1);
                a += __shfl_xor_sync(0xffffffff, a, 2);
                if ((lane & 3) == 0)
                    out[(size_t)(m_base + mrow) * DOUT + o_base + o_loc] = a;
            }
        }
    }
}

// ---------------- launch ----------------
extern "C" void kernel_launch(void* const* d_in, const int* in_sizes, int n_in,
                              void* d_out, int out_size) {
    const float* x  = (const float*)d_in[0];   // [4096,1024]
    const float* gw = (const float*)d_in[1];   // [1024,32]
    const float* gb = (const float*)d_in[2];   // [32]
    const float* pw = (const float*)d_in[3];   // [1024,1024,32]
    const float* pb = (const float*)d_in[4];   // [1024,32]
    float* out = (float*)d_out;                // [4096,1024]

    cudaFuncSetAttribute(moe_gemm_kernel,
                         cudaFuncAttributeMaxDynamicSharedMemorySize, SMEM_TOTAL);

    gating_kernel<<<BROWS / 4, 128>>>(x, gw, gb);
    pack_pw_kernel<<<dim3(DOUT, DIN / 64), 256>>>(pw);
    moe_gemm_kernel<<<32 * (NTOT / NT), 256, SMEM_TOTAL>>>(out, pb);
}

// round 9
// speedup vs baseline: 1.0756x; 1.0756x over previous
#include <cuda_runtime.h>
#include <cuda_fp16.h>
#include <cstdint>
#include <cstddef>

#define BROWS 4096
#define DIN   1024
#define DOUT  1024
#define LEAF  32
#define NTOT  (DOUT * LEAF)   // 32768

// ---------------- scratch (device globals: allocation-free) ----------------
__device__ __align__(128) __half d_xb[(size_t)BROWS * DIN];     // 8 MB   x fp16
__device__ __align__(128) __half d_pwb[(size_t)NTOT * DIN];     // 64 MB  pw packed [n=o*32+l][k=i]
__device__ __align__(128) float  d_gate[(size_t)BROWS * LEAF];  // 512 KB gates

// ---------------- helpers ----------------
static __device__ __forceinline__ uint32_t smem_u32(const void* p) {
    uint32_t a;
    asm("{ .reg .u64 t; cvta.to.shared.u64 t, %1; cvt.u32.u64 %0, t; }" : "=r"(a) : "l"(p));
    return a;
}
static __device__ __forceinline__ uint32_t swz(uint32_t o) {     // Swizzle<3,4,3>, 128B rows
    return o ^ ((o >> 3) & 0x70);
}
static __device__ __forceinline__ void cp_async16(uint32_t s, const void* g) {
    asm volatile("cp.async.cg.shared.global [%0], [%1], 16;" :: "r"(s), "l"(g));
}
static __device__ __forceinline__ void ldsm4(uint32_t* r, uint32_t addr) {
    asm volatile("ldmatrix.sync.aligned.m8n8.x4.shared.b16 {%0,%1,%2,%3}, [%4];"
                 : "=r"(r[0]), "=r"(r[1]), "=r"(r[2]), "=r"(r[3]) : "r"(addr));
}
static __device__ __forceinline__ void mma16816(float* d, const uint32_t* a,
                                                uint32_t b0, uint32_t b1) {
    asm volatile("mma.sync.aligned.m16n8k16.row.col.f32.f16.f16.f32 "
                 "{%0,%1,%2,%3}, {%4,%5,%6,%7}, {%8,%9}, {%0,%1,%2,%3};"
                 : "+f"(d[0]), "+f"(d[1]), "+f"(d[2]), "+f"(d[3])
                 : "r"(a[0]), "r"(a[1]), "r"(a[2]), "r"(a[3]), "r"(b0), "r"(b1));
}

// ---------------- kernel 1: gating softmax + x fp32->fp16 (fused) ----------------
__global__ void gating_kernel(const float* __restrict__ x, const float* __restrict__ gw,
                              const float* __restrict__ gb) {
    int row  = (blockIdx.x * blockDim.x + threadIdx.x) >> 5;
    int lane = threadIdx.x & 31;
    if (row >= BROWS) return;
    const float4* xr = reinterpret_cast<const float4*>(x + (size_t)row * DIN);
    // 4 independent accumulators: break the serial FMA dependency chain
    float a0 = gb[lane], a1 = 0.f, a2 = 0.f, a3 = 0.f;
    #pragma unroll 4
    for (int j = 0; j < DIN / 4; j += 4) {
        float4 v0 = xr[j], v1 = xr[j + 1], v2 = xr[j + 2], v3 = xr[j + 3];
        const float* g0 = gw + (j * 4) * LEAF + lane;
        a0 = fmaf(v0.x, g0[0 * LEAF], a0); a0 = fmaf(v0.y, g0[1 * LEAF], a0);
        a0 = fmaf(v0.z, g0[2 * LEAF], a0); a0 = fmaf(v0.w, g0[3 * LEAF], a0);
        a1 = fmaf(v1.x, g0[4 * LEAF], a1); a1 = fmaf(v1.y, g0[5 * LEAF], a1);
        a1 = fmaf(v1.z, g0[6 * LEAF], a1); a1 = fmaf(v1.w, g0[7 * LEAF], a1);
        a2 = fmaf(v2.x, g0[8 * LEAF], a2); a2 = fmaf(v2.y, g0[9 * LEAF], a2);
        a2 = fmaf(v2.z, g0[10 * LEAF], a2); a2 = fmaf(v2.w, g0[11 * LEAF], a2);
        a3 = fmaf(v3.x, g0[12 * LEAF], a3); a3 = fmaf(v3.y, g0[13 * LEAF], a3);
        a3 = fmaf(v3.z, g0[14 * LEAF], a3); a3 = fmaf(v3.w, g0[15 * LEAF], a3);
    }
    float acc = (a0 + a1) + (a2 + a3);
    // second pass: lane-owned chunks, L1-hot, coalesced 8B stores
    __half2* hp = reinterpret_cast<__half2*>(d_xb + (size_t)row * DIN);
    #pragma unroll
    for (int jj = 0; jj < 8; ++jj) {
        int j = jj * 32 + lane;
        float4 xv = xr[j];
        hp[j * 2 + 0] = __floats2half2_rn(xv.x, xv.y);
        hp[j * 2 + 1] = __floats2half2_rn(xv.z, xv.w);
    }
    float m = acc;
    #pragma unroll
    for (int o = 16; o; o >>= 1) m = fmaxf(m, __shfl_xor_sync(0xffffffff, m, o));
    float e = expf(acc - m);
    float s = e;
    #pragma unroll
    for (int o = 16; o; o >>= 1) s += __shfl_xor_sync(0xffffffff, s, o);
    d_gate[(size_t)row * LEAF + lane] = e / s;
}

// ---------------- kernel 2: pack pw [O,I,L] fp32 -> pwb [(o*32+l), i] fp16 ----------------
__global__ void pack_pw_kernel(const float* __restrict__ pw) {
    __shared__ float tile[64][33];                        // 64 i  x 32 l  (padded)
    const int o   = blockIdx.x;                           // 0..1023
    const int i0  = blockIdx.y * 64;                      // 0..960
    const int tid = threadIdx.x;                          // 256 threads
    const float* src = pw + ((size_t)o * DIN + i0) * LEAF;
    #pragma unroll
    for (int u = 0; u < 8; ++u) {                         // 2048 coalesced fp32 reads
        int idx = u * 256 + tid;
        tile[idx >> 5][idx & 31] = src[idx];
    }
    __syncthreads();
    __half2* dst2 = reinterpret_cast<__half2*>(d_pwb + ((size_t)o * LEAF) * DIN + i0);
    #pragma unroll
    for (int u = 0; u < 4; ++u) {                         // 1024 coalesced half2 writes
        int idx = u * 256 + tid;
        int l = idx >> 5, p = idx & 31;
        dst2[(size_t)l * (DIN / 2) + p] =
            __floats2half2_rn(tile[2 * p][l], tile[2 * p + 1][l]);
    }
}

// ---------------- kernel 3: mma.sync GEMM, 2 CTA/SM, warp tile 64x64 ----------------
#define MT  128
#define NT  128
#define KT  64                       // halves per k-tile (128 B rows)
#define KI  (DIN / KT)               // 16
#define STG 3
#define SA_BYTES    (MT * KT * 2)    // 16384
#define SB_BYTES    (NT * KT * 2)    // 16384
#define STAGE_BYTES (SA_BYTES + SB_BYTES)          // 32768
#define SMEM_TOTAL  (STG * STAGE_BYTES)            // 98304 -> 2 CTAs/SM

static __device__ __forceinline__ void load_tile(uint32_t sb, int tid,
                                                 int m_base, int n_base, int ki, int buf) {
    const uint32_t abase = sb + buf * STAGE_BYTES;
    const uint32_t bbase = abase + SA_BYTES;
    const __half* ga  = d_xb  + (size_t)m_base * DIN + ki * KT;
    const __half* gbp = d_pwb + (size_t)n_base * DIN + ki * KT;
    #pragma unroll
    for (int u = 0; u < 16; ++u) {                        // 2048 x 16B chunks / 128 thr
        const int idx = u * 128 + tid;
        if (idx < 1024) {                                 // A: 128 rows x 8 chunks
            const int r = idx >> 3, c = idx & 7;
            cp_async16(abase + swz((uint32_t)(r * 128 + c * 16)),
                       ga + (size_t)r * DIN + c * 8);
        } else {                                          // B: 128 rows x 8 chunks
            const int j = idx - 1024;
            const int r = j >> 3, c = j & 7;
            cp_async16(bbase + swz((uint32_t)(r * 128 + c * 16)),
                       gbp + (size_t)r * DIN + c * 8);
        }
    }
}

__global__ void __launch_bounds__(128, 2)
moe_gemm_kernel(float* __restrict__ out, const float* __restrict__ pb) {
    extern __shared__ char smem[];
    const uint32_t sb = smem_u32(smem);
    const int tid    = threadIdx.x;
    const int lane   = tid & 31;
    const int wid    = tid >> 5;                // 4 warps: 2(m) x 2(n)
    const int warp_n = wid & 1;                 // 2 n-warps x 64 cols
    const int warp_m = wid >> 1;                // 2 m-warps x 64 rows
    const int m_tile = blockIdx.x & 31;         // bid = n_tile*32 + m_tile (B panel L2 reuse)
    const int n_tile = blockIdx.x >> 5;
    const int m_base = m_tile * MT;
    const int n_base = n_tile * NT;
    const int o_base = n_tile * 4;              // NT=128 cols = 4 outputs x 32 leaves

    // prologue: stages 0..1
    #pragma unroll
    for (int p = 0; p < STG - 1; ++p) {
        load_tile(sb, tid, m_base, n_base, p, p);
        asm volatile("cp.async.commit_group;" ::: "memory");
    }

    float acc[4][8][4];                         // 4 m-frags x 8 n8-frags x 4 regs
    #pragma unroll
    for (int a = 0; a < 4; ++a)
        #pragma unroll
        for (int b = 0; b < 8; ++b)
            #pragma unroll
            for (int c = 0; c < 4; ++c) acc[a][b][c] = 0.f;

    const uint32_t arow = (uint32_t)(warp_m * 64 + (lane & 15));
    const uint32_t brow = (uint32_t)(warp_n * 64 + (lane & 7) + ((lane & 16) ? 8 : 0));

    #pragma unroll 1
    for (int t = 0; t < KI; ++t) {
        const int buf = t % STG;
        asm volatile("cp.async.wait_group %0;" :: "n"(STG - 2) : "memory");
        __syncthreads();
        const uint32_t abase = sb + buf * STAGE_BYTES;
        const uint32_t bbase = abase + SA_BYTES;
        #pragma unroll
        for (int ks = 0; ks < 4; ++ks) {
            const uint32_t akh = (uint32_t)(ks * 16 + ((lane >> 4) << 3));
            const uint32_t bkh = (uint32_t)(ks * 16 + ((lane >> 3) & 1) * 8);
            uint32_t A[4][4];
            #pragma unroll
            for (int q = 0; q < 4; ++q)
                ldsm4(A[q], abase + swz((arow + (uint32_t)(q * 16)) * 128 + akh * 2));
            uint32_t Bf[4][4];
            #pragma unroll
            for (int q = 0; q < 4; ++q)
                ldsm4(Bf[q], bbase + swz((brow + (uint32_t)(q * 16)) * 128 + bkh * 2));
            #pragma unroll
            for (int mf = 0; mf < 4; ++mf)
                #pragma unroll
                for (int nf = 0; nf < 8; ++nf)
                    mma16816(acc[mf][nf], A[mf],
                             Bf[nf >> 1][(nf & 1) * 2], Bf[nf >> 1][(nf & 1) * 2 + 1]);
        }
        if (t + STG - 1 < KI)
            load_tile(sb, tid, m_base, n_base, t + STG - 1, (t + STG - 1) % STG);
        asm volatile("cp.async.commit_group;" ::: "memory");   // empty group keeps counts
    }

    // drain cp.async, then reuse stage smem for epilogue tables
    asm volatile("cp.async.wait_group 0;" ::: "memory");
    __syncthreads();
    float* gs  = reinterpret_cast<float*>(smem);               // [128][33] = 16896 B
    float* pbs = reinterpret_cast<float*>(smem + 16896);       // [4][33]
    #pragma unroll
    for (int i = tid; i < MT * LEAF; i += 128) {
        int r = i >> 5, l = i & 31;
        gs[r * 33 + l] = d_gate[(size_t)(m_base + r) * LEAF + l];
    }
    pbs[(tid >> 5) * 33 + (tid & 31)] = pb[(o_base + (tid >> 5)) * LEAF + (tid & 31)];
    __syncthreads();

    // epilogue: warp covers cols [warp_n*64, +64) = 2 outputs x 32 leaves
    #pragma unroll
    for (int mf = 0; mf < 4; ++mf) {
        #pragma unroll
        for (int rh = 0; rh < 2; ++rh) {
            const int mrow = warp_m * 64 + mf * 16 + (lane >> 2) + rh * 8;
            #pragma unroll
            for (int og = 0; og < 2; ++og) {
                const int o_loc = warp_n * 2 + og;
                float a = 0.f;
                #pragma unroll
                for (int nf4 = 0; nf4 < 4; ++nf4) {
                    const int nf = og * 4 + nf4;
                    const int l  = nf4 * 8 + (lane & 3) * 2;
                    a = fmaf(acc[mf][nf][rh * 2 + 0] + pbs[o_loc * 33 + l],
                             gs[mrow * 33 + l], a);
                    a = fmaf(acc[mf][nf][rh * 2 + 1] + pbs[o_loc * 33 + l + 1],
                             gs[mrow * 33 + l + 1], a);
                }
                a += __shfl_xor_sync(0xffffffff, a, 1);
                a += __shfl_xor_sync(0xffffffff, a, 2);
                if ((lane & 3) == 0)
                    out[(size_t)(m_base + mrow) * DOUT + o_base + o_loc] = a;
            }
        }
    }
}

// ---------------- launch ----------------
extern "C" void kernel_launch(void* const* d_in, const int* in_sizes, int n_in,
                              void* d_out, int out_size) {
    const float* x  = (const float*)d_in[0];   // [4096,1024]
    const float* gw = (const float*)d_in[1];   // [1024,32]
    const float* gb = (const float*)d_in[2];   // [32]
    const float* pw = (const float*)d_in[3];   // [1024,1024,32]
    const float* pb = (const float*)d_in[4];   // [1024,32]
    float* out = (float*)d_out;                // [4096,1024]

    cudaFuncSetAttribute(moe_gemm_kernel,
                         cudaFuncAttributeMaxDynamicSharedMemorySize, SMEM_TOTAL);

    gating_kernel<<<BROWS / 4, 128>>>(x, gw, gb);
    pack_pw_kernel<<<dim3(DOUT, DIN / 64), 256>>>(pw);
    moe_gemm_kernel<<<32 * (NTOT / NT), 128, SMEM_TOTAL>>>(out, pb);
}